// round 11
// baseline (speedup 1.0000x reference)
#include <cuda_runtime.h>
#include <cuda_fp16.h>
#include <cstdint>

// B=2, N=1024, C=128, H1=128, H2=64
//   aL[b,i,h] = x[b,i]@W1[:C] + b1 ; aR[b,j,h] = x[b,j]@W1[C:]
//   y[b,i,j] = relu(relu(aL_i + aR_j) @ W2 + b2) @ W3 + b3   (j>i else 0)
// R11 (base = R10, 58.8us pair): split CTA into 2 independent 4-warp groups,
// each with its own 16ix16j tile stream, double buffers, and named barrier.
// Groups de-phase -> one group's MMAs cover the other's epilogue/staging.
// W2 nt0..3 regs now loaded from gmem; smem W2 keeps only rows 32..63.

#define Bb 2
#define Nn 1024
#define Cc 128
#define H1 128
#define H2 64

#define TI 16
#define TJ 16
#define NACT_G  4160   // active 16x16 tiles: 2 * 64*65/2
#define HALF_G  2080
#define NMASK_G 4032   // masked tiles: 2 * 64*63/2

// scratch (device globals; fp16 pairs, k-permuted)
__device__ __align__(16) __half2 g_aLh[Bb * Nn * 64];
__device__ __align__(16) __half2 g_aRh[Bb * Nn * 64];
__device__ __align__(16) __half2 g_W2h[H2 * 64];

__device__ __forceinline__ int slotperm(int j) {
    int jj = j & 7;
    return (j & ~7) | (jj < 4 ? (jj << 1) : (((jj - 4) << 1) | 1));
}

__device__ __forceinline__ uint32_t h2_relu_add(uint32_t x, uint32_t y) {
    __half2 a = *reinterpret_cast<__half2*>(&x);
    __half2 b = *reinterpret_cast<__half2*>(&y);
    __half2 r = __hmax2(__hadd2(a, b), __float2half2_rn(0.f));
    return *reinterpret_cast<uint32_t*>(&r);
}

__device__ __forceinline__ void mma_f16(float c[4], const uint32_t a[4],
                                        uint32_t b0, uint32_t b1) {
    asm volatile(
        "mma.sync.aligned.m16n8k16.row.col.f32.f16.f16.f32 "
        "{%0,%1,%2,%3},{%4,%5,%6,%7},{%8,%9},{%0,%1,%2,%3};"
        : "+f"(c[0]), "+f"(c[1]), "+f"(c[2]), "+f"(c[3])
        : "r"(a[0]), "r"(a[1]), "r"(a[2]), "r"(a[3]), "r"(b0), "r"(b1));
}

__device__ __forceinline__ uint32_t smem_u32(const void* p) {
    uint32_t a;
    asm("{ .reg .u64 t; cvta.to.shared.u64 t, %1; cvt.u32.u64 %0, t; }"
        : "=r"(a) : "l"(p));
    return a;
}
__device__ __forceinline__ void cpasync16(uint32_t dst, const void* src) {
    asm volatile("cp.async.cg.shared.global [%0], [%1], 16;"
                 :: "r"(dst), "l"(src));
}
#define CP_COMMIT() asm volatile("cp.async.commit_group;" ::: "memory")
#define CP_WAIT1()  asm volatile("cp.async.wait_group 1;" ::: "memory")
#define GBAR(id)    asm volatile("bar.sync %0, 128;" :: "r"(id) : "memory")

// ---------------------------------------------------------------------------
// Prep (256 threads/CTA): [0,128) aL/aR rows (16/CTA); [128,144) W2 convert.
// ---------------------------------------------------------------------------
#define ROW_BLKS 128
#define W2_BLKS 16
#define PREP_GRID (ROW_BLKS + W2_BLKS)

__global__ void __launch_bounds__(256)
prep_kernel(const float* __restrict__ x,
            const float* __restrict__ W1,
            const float* __restrict__ b1,
            const float* __restrict__ W2) {
    const int blk = blockIdx.x;
    const int tid = threadIdx.x;

    if (blk < ROW_BLKS) {
        __shared__ float sx[16][Cc];
        __shared__ float res[16][256];
        const int r0 = blk * 16;
        {
            const float4* x4 = (const float4*)x;
#pragma unroll
            for (int u = 0; u < 2; u++)
                ((float4*)sx)[tid + 256 * u] = x4[r0 * 32 + tid + 256 * u];
        }
        __syncthreads();

        const int side = tid >> 7;
        const int h = tid & 127;
        const float* Wp = W1 + (side ? (Cc * H1 + h) : h);
        float acc[16];
        const float init = side ? 0.f : b1[h];
#pragma unroll
        for (int r = 0; r < 16; r++) acc[r] = init;

#pragma unroll 4
        for (int c = 0; c < Cc; c += 4) {
            float w0 = __ldg(&Wp[(c + 0) * H1]);
            float w1 = __ldg(&Wp[(c + 1) * H1]);
            float w2 = __ldg(&Wp[(c + 2) * H1]);
            float w3 = __ldg(&Wp[(c + 3) * H1]);
#pragma unroll
            for (int r = 0; r < 16; r++) {
                float4 sv = *(const float4*)&sx[r][c];
                float a = acc[r];
                a = fmaf(sv.x, w0, a);
                a = fmaf(sv.y, w1, a);
                a = fmaf(sv.z, w2, a);
                a = fmaf(sv.w, w3, a);
                acc[r] = a;
            }
        }
#pragma unroll
        for (int r = 0; r < 16; r++) res[r][side * 128 + h] = acc[r];
        __syncthreads();

#pragma unroll
        for (int u = 0; u < 8; u++) {
            int idx = tid + 256 * u;
            int row = idx >> 7;
            int rem = idx & 127;
            int sd = rem >> 6;
            int j = rem & 63;
            __half2 v = __floats2half2_rn(res[row][sd * 128 + 2 * j],
                                          res[row][sd * 128 + 2 * j + 1]);
            (sd ? g_aRh : g_aLh)[(size_t)(r0 + row) * 64 + slotperm(j)] = v;
        }
    } else {
        int idx = (blk - ROW_BLKS) * 256 + tid;
        int n = idx >> 6;
        int j = idx & 63;
        g_W2h[n * 64 + slotperm(j)] =
            __floats2half2_rn(W2[(2 * j) * H2 + n], W2[(2 * j + 1) * H2 + n]);
    }
}

// ---------------------------------------------------------------------------
// Persistent pair kernel. 256 threads = 2 groups x 4 warps.
// Group tile 16i x 16j = 256 pairs; warp w: m-tiles il=4w..4w+3, nt=8.
// ---------------------------------------------------------------------------
#define AR_STRIDE 34     // uint2 per aR row (17 uint4)
#define W2_STRIDE 34

struct SmemLayout {
    uint2 w2hi[32 * W2_STRIDE];        // W2 rows 32..63 (8704 B)
    uint2 aL[2][2][TI * 32];           // [group][buf] 4096 B each
    uint2 aR[2][2][TJ * AR_STRIDE];    // [group][buf] 4352 B each
    float b2s[H2];
    float w3s[H2];
};

// active decode (per batch): C(it) = it*(129-it)/2; jt = it + (aa - C(it))
__device__ __forceinline__ void decode_tile(int aa, int& it, int& jt) {
    it = (int)((129.f - sqrtf(16641.f - 8.f * (float)aa)) * 0.5f);
    while ((it + 1) * (128 - it) / 2 <= aa) it++;
    while (it * (129 - it) / 2 > aa) it--;
    jt = it + (aa - it * (129 - it) / 2);
}

__global__ void __launch_bounds__(256)
pair_kernel(const float* __restrict__ b2,
            const float* __restrict__ W3,
            const float* __restrict__ b3,
            float* __restrict__ out) {
    __shared__ SmemLayout sm;

    const int tid = threadIdx.x;
    const int g = tid >> 7;        // group 0/1
    const int gtid = tid & 127;
    const int wid = gtid >> 5;     // warp in group: 0..3
    const int lane = tid & 31;
    const int p = lane >> 2;
    const int q = lane & 3;

    // ---- CTA-wide init: W2 rows 32..63 to smem, biases ----
    {
        const uint2* gW2 = (const uint2*)g_W2h;
        for (int i = tid; i < 32 * 32; i += 256) {
            int r = i >> 5, c = i & 31;
            sm.w2hi[r * W2_STRIDE + c] = gW2[(32 + r) * 32 + c];
        }
        if (tid < H2) {
            sm.b2s[tid] = b2[tid];
            sm.w3s[tid] = W3[tid];
        }
    }
    const float b3v = __ldg(&b3[0]);

    // ---- zero fully-masked tiles (16x16, jt < it) ----
    {
        float4* out4 = (float4*)out;
        for (int m = blockIdx.x; m < NMASK_G; m += gridDim.x) {
            int bz = (m >= NMASK_G / 2);
            int mm = m - (bz ? NMASK_G / 2 : 0);
            int itz = (int)((1.f + sqrtf(1.f + 8.f * (float)mm)) * 0.5f);
            while (itz * (itz + 1) / 2 <= mm) itz++;
            while (itz * (itz - 1) / 2 > mm) itz--;
            int jtz = mm - itz * (itz - 1) / 2;
            if (tid < 64) {
                int r = tid >> 2, c4 = tid & 3;
                out4[(size_t)((bz << 10) + itz * TI + r) * 256 + jtz * 4 + c4] =
                    make_float4(0.f, 0.f, 0.f, 0.f);
            }
        }
    }
    __syncthreads();   // w2hi/biases visible; groups diverge after this

    // ---- persistent W2 fragments nt 0..3 from gmem (64 regs) ----
    uint32_t w2r[8][4][2];
    {
        const uint2* gW2 = (const uint2*)g_W2h;
#pragma unroll
        for (int ks = 0; ks < 8; ks++)
#pragma unroll
            for (int ntl = 0; ntl < 4; ntl++) {
                uint2 bb = __ldg(&gW2[(ntl * 8 + p) * 32 + 4 * ks + q]);
                w2r[ks][ntl][0] = bb.x;
                w2r[ks][ntl][1] = bb.y;
            }
    }

    const int il0 = 4 * wid;
    const int bar = 1 + g;
    const int Gid = blockIdx.x + g * gridDim.x;     // global group id
    const int Gstep = 2 * gridDim.x;

    // staging chunks (uint4): aL 256 chunks, aR 256 chunks; 128 threads, 2 each
    auto issue_stage = [&](int buf, int b, int i0, int j0) {
        const uint4* srcL = (const uint4*)(g_aLh + ((size_t)((b << 10) + i0) << 6));
        const uint4* srcR = (const uint4*)(g_aRh + ((size_t)((b << 10) + j0) << 6));
        uint32_t dL = smem_u32(&sm.aL[g][buf][0]);
        uint32_t dR = smem_u32(&sm.aR[g][buf][0]);
#pragma unroll
        for (int u = 0; u < 2; u++) {
            int c = gtid + 128 * u;
            cpasync16(dL + (uint32_t)(c * 16), srcL + c);
            int r = c >> 4, cc = c & 15;
            cpasync16(dR + (uint32_t)((r * 17 + cc) * 16), srcR + c);
        }
    };

    int buf = 0;
    int curB = 0, curI0 = 0, curJ0 = 0;
    {
        int a0 = Gid;
        if (a0 < NACT_G) {
            int b = (a0 >= HALF_G);
            int aa = a0 - (b ? HALF_G : 0);
            int it, jt;
            decode_tile(aa, it, jt);
            curB = b; curI0 = it * TI; curJ0 = jt * TJ;
            issue_stage(0, curB, curI0, curJ0);
        }
        CP_COMMIT();
    }

    for (int a = Gid; a < NACT_G; a += Gstep) {
        const int b  = curB;
        const int i0 = curI0;
        const int j0 = curJ0;

        {
            int an = a + Gstep;
            if (an < NACT_G) {
                int bn = (an >= HALF_G);
                int aan = an - (bn ? HALF_G : 0);
                int itn, jtn;
                decode_tile(aan, itn, jtn);
                curB = bn; curI0 = itn * TI; curJ0 = jtn * TJ;
                issue_stage(buf ^ 1, bn, curI0, curJ0);
            }
            CP_COMMIT();
        }
        CP_WAIT1();
        GBAR(bar);          // current buffer visible to the whole group

        const uint2* aLb = sm.aL[g][buf];
        const uint2* aRb = sm.aR[g][buf];

        float acc[4][8][4];
#pragma unroll
        for (int mt = 0; mt < 4; mt++)
#pragma unroll
            for (int nt = 0; nt < 8; nt++)
#pragma unroll
                for (int e = 0; e < 4; e++) acc[mt][nt][e] = 0.f;

        // ---- kstep loop with one-stage register pipeline ----
        uint2 Rp_c, Rp8_c, La_c0, La_c1, La_c2, La_c3;
        {
            const int kf = q;
            Rp_c  = aRb[p * AR_STRIDE + kf];
            Rp8_c = aRb[(p + 8) * AR_STRIDE + kf];
            La_c0 = aLb[(il0 + 0) * 32 + kf];
            La_c1 = aLb[(il0 + 1) * 32 + kf];
            La_c2 = aLb[(il0 + 2) * 32 + kf];
            La_c3 = aLb[(il0 + 3) * 32 + kf];
        }
#pragma unroll
        for (int ks = 0; ks < 8; ks++) {
            uint2 Rp_n, Rp8_n, La_n0, La_n1, La_n2, La_n3;
            if (ks < 7) {
                const int kf = 4 * (ks + 1) + q;
                Rp_n  = aRb[p * AR_STRIDE + kf];
                Rp8_n = aRb[(p + 8) * AR_STRIDE + kf];
                La_n0 = aLb[(il0 + 0) * 32 + kf];
                La_n1 = aLb[(il0 + 1) * 32 + kf];
                La_n2 = aLb[(il0 + 2) * 32 + kf];
                La_n3 = aLb[(il0 + 3) * 32 + kf];
            }

            uint32_t a4[4][4];
            {
                uint2 Ls[4] = {La_c0, La_c1, La_c2, La_c3};
#pragma unroll
                for (int mt = 0; mt < 4; mt++) {
                    a4[mt][0] = h2_relu_add(Ls[mt].x, Rp_c.x);
                    a4[mt][1] = h2_relu_add(Ls[mt].x, Rp8_c.x);
                    a4[mt][2] = h2_relu_add(Ls[mt].y, Rp_c.y);
                    a4[mt][3] = h2_relu_add(Ls[mt].y, Rp8_c.y);
                }
            }

#pragma unroll
            for (int ntl = 0; ntl < 4; ntl++)
#pragma unroll
                for (int mt = 0; mt < 4; mt++)
                    mma_f16(acc[mt][ntl], a4[mt],
                            w2r[ks][ntl][0], w2r[ks][ntl][1]);
#pragma unroll
            for (int ntl = 4; ntl < 8; ntl++) {
                uint2 bb = sm.w2hi[((ntl - 4) * 8 + p) * W2_STRIDE + 4 * ks + q];
#pragma unroll
                for (int mt = 0; mt < 4; mt++)
                    mma_f16(acc[mt][ntl], a4[mt], bb.x, bb.y);
            }

            Rp_c = Rp_n; Rp8_c = Rp8_n;
            La_c0 = La_n0; La_c1 = La_n1; La_c2 = La_n2; La_c3 = La_n3;
        }

        // ---- epilogue ----
#pragma unroll
        for (int mt = 0; mt < 4; mt++) {
            float slo = 0.f, shi = 0.f;
#pragma unroll
            for (int nt = 0; nt < 8; nt++) {
                int g0 = nt * 8 + 2 * q;
                float b20 = sm.b2s[g0], b21 = sm.b2s[g0 + 1];
                float w30 = sm.w3s[g0], w31 = sm.w3s[g0 + 1];
                slo = fmaf(fmaxf(acc[mt][nt][0] + b20, 0.f), w30, slo);
                slo = fmaf(fmaxf(acc[mt][nt][1] + b21, 0.f), w31, slo);
                shi = fmaf(fmaxf(acc[mt][nt][2] + b20, 0.f), w30, shi);
                shi = fmaf(fmaxf(acc[mt][nt][3] + b21, 0.f), w31, shi);
            }
            slo += __shfl_xor_sync(0xFFFFFFFFu, slo, 1);
            slo += __shfl_xor_sync(0xFFFFFFFFu, slo, 2);
            shi += __shfl_xor_sync(0xFFFFFFFFu, shi, 1);
            shi += __shfl_xor_sync(0xFFFFFFFFu, shi, 2);
            if (q == 0) {
                int gi = i0 + il0 + mt;
                int gjlo = j0 + p;
                int gjhi = gjlo + 8;
                size_t base = ((size_t)((b << 10) + gi)) << 10;
                out[base + gjlo] = (gjlo > gi) ? (slo + b3v) : 0.f;
                out[base + gjhi] = (gjhi > gi) ? (shi + b3v) : 0.f;
            }
        }
        GBAR(bar);   // group reads of `buf` done before it is re-staged
        buf ^= 1;
    }
}

// ---------------------------------------------------------------------------
extern "C" void kernel_launch(void* const* d_in, const int* in_sizes, int n_in,
                              void* d_out, int out_size) {
    const float* x  = (const float*)d_in[0];
    const float* W1 = (const float*)d_in[1];
    const float* b1 = (const float*)d_in[2];
    const float* W2 = (const float*)d_in[3];
    const float* b2 = (const float*)d_in[4];
    const float* W3 = (const float*)d_in[5];
    const float* b3 = (const float*)d_in[6];
    float* out = (float*)d_out;

    prep_kernel<<<PREP_GRID, 256>>>(x, W1, b1, W2);
    pair_kernel<<<152, 256>>>(b2, W3, b3, out);
}

// round 12
// speedup vs baseline: 1.0219x; 1.0219x over previous
#include <cuda_runtime.h>
#include <cuda_fp16.h>
#include <cstdint>

// B=2, N=1024, C=128, H1=128, H2=64
//   aL[b,i,h] = x[b,i]@W1[:C] + b1 ; aR[b,j,h] = x[b,j]@W1[C:]
//   y[b,i,j] = relu(relu(aL_i + aR_j) @ W2 + b2) @ W3 + b3   (j>i else 0)
// R12: single fused kernel. Phase A = prep (aL/aR, W2 convert, masked-tile
// zeroing); device spin grid-barrier (self-resetting, graph-replay safe);
// Phase B = R10 pair body (best: 58.8us). Removes the constant ~11-12us
// prep/launch gap seen in every round. grid=148, 1 CTA/SM -> co-residency
// guaranteed, barrier cannot deadlock.

#define Bb 2
#define Nn 1024
#define Cc 128
#define H1 128
#define H2 64

#define TI 32
#define TJ 16
#define NACT  2112     // active tiles: 2 * 1056
#define NMASK 1984     // fully-masked tiles: 2 * 992
#define HALF_ACT 1056
#define GRID 148

// scratch (device globals; fp16 pairs, k-permuted)
__device__ __align__(16) __half2 g_aLh[Bb * Nn * 64];
__device__ __align__(16) __half2 g_aRh[Bb * Nn * 64];
__device__ __align__(16) __half2 g_W2h[H2 * 64];
__device__ unsigned g_cnt = 0u;
__device__ unsigned g_done = 0u;

__device__ __forceinline__ int slotperm(int j) {
    int jj = j & 7;
    return (j & ~7) | (jj < 4 ? (jj << 1) : (((jj - 4) << 1) | 1));
}

__device__ __forceinline__ uint32_t h2_relu_add(uint32_t x, uint32_t y) {
    __half2 a = *reinterpret_cast<__half2*>(&x);
    __half2 b = *reinterpret_cast<__half2*>(&y);
    __half2 r = __hmax2(__hadd2(a, b), __float2half2_rn(0.f));
    return *reinterpret_cast<uint32_t*>(&r);
}

__device__ __forceinline__ void mma_f16(float c[4], const uint32_t a[4],
                                        uint32_t b0, uint32_t b1) {
    asm volatile(
        "mma.sync.aligned.m16n8k16.row.col.f32.f16.f16.f32 "
        "{%0,%1,%2,%3},{%4,%5,%6,%7},{%8,%9},{%0,%1,%2,%3};"
        : "+f"(c[0]), "+f"(c[1]), "+f"(c[2]), "+f"(c[3])
        : "r"(a[0]), "r"(a[1]), "r"(a[2]), "r"(a[3]), "r"(b0), "r"(b1));
}

__device__ __forceinline__ uint32_t smem_u32(const void* p) {
    uint32_t a;
    asm("{ .reg .u64 t; cvta.to.shared.u64 t, %1; cvt.u32.u64 %0, t; }"
        : "=r"(a) : "l"(p));
    return a;
}
__device__ __forceinline__ void cpasync16(uint32_t dst, const void* src) {
    asm volatile("cp.async.cg.shared.global [%0], [%1], 16;"
                 :: "r"(dst), "l"(src));
}
#define CP_COMMIT() asm volatile("cp.async.commit_group;" ::: "memory")
#define CP_WAIT1()  asm volatile("cp.async.wait_group 1;" ::: "memory")

#define AR_STRIDE 34     // uint2 per aR row (17 uint4)
#define W2_STRIDE 34

struct SmemPair {
    uint2 w2[H2 * W2_STRIDE];     // 17408 B
    uint2 aL[2][TI * 32];         // 2 x 8192 B
    uint2 aR[2][TJ * AR_STRIDE];  // 2 x 4352 B
    float b2s[H2];
    float w3s[H2];
};
struct SmemPrep {
    float sx[14][Cc];             // 7168 B
    float res[14][256];           // 14336 B
};
union SmemAll {
    SmemPair pair;
    SmemPrep prep;
};

// active decode: C(it) = it*(65-it); jt = 2it + (aa - C(it))
__device__ __forceinline__ void decode_tile(int aa, int& it, int& jt) {
    it = (int)((65.f - sqrtf(4225.f - 4.f * (float)aa)) * 0.5f);
    while ((it + 1) * (64 - it) <= aa) it++;
    while (it * (65 - it) > aa) it--;
    jt = 2 * it + (aa - it * (65 - it));
}

__global__ void __launch_bounds__(256)
fused_kernel(const float* __restrict__ x,
             const float* __restrict__ W1,
             const float* __restrict__ b1,
             const float* __restrict__ W2,
             const float* __restrict__ b2,
             const float* __restrict__ W3,
             const float* __restrict__ b3,
             float* __restrict__ out) {
    __shared__ SmemAll smu;

    const int tid = threadIdx.x;
    const int bid = blockIdx.x;
    const int wid = tid >> 5;
    const int lane = tid & 31;
    const int p = lane >> 2;
    const int q = lane & 3;

    // ======================= PHASE A: prep =======================
    {
        SmemPrep* pr = &smu.prep;
        const int r0 = bid * 14;                  // 148*14 = 2072 >= 2048
        const int nrows = min(14, Bb * Nn - r0);  // may be <= 0

        if (nrows > 0) {
            // stage x rows (448 float4 max)
            const float4* x4 = (const float4*)x;
#pragma unroll
            for (int u = 0; u < 2; u++) {
                int c = tid + 256 * u;
                if (c < 448 && (r0 * 32 + c) < Bb * Nn * 32)
                    ((float4*)pr->sx)[c] = x4[r0 * 32 + c];
            }
            __syncthreads();

            const int side = tid >> 7;
            const int h = tid & 127;
            const float* Wp = W1 + (side ? (Cc * H1 + h) : h);
            float acc[14];
            const float init = side ? 0.f : b1[h];
#pragma unroll
            for (int r = 0; r < 14; r++) acc[r] = init;

#pragma unroll 4
            for (int c = 0; c < Cc; c += 4) {
                float w0 = __ldg(&Wp[(c + 0) * H1]);
                float w1 = __ldg(&Wp[(c + 1) * H1]);
                float w2 = __ldg(&Wp[(c + 2) * H1]);
                float w3 = __ldg(&Wp[(c + 3) * H1]);
#pragma unroll
                for (int r = 0; r < 14; r++) {
                    float4 sv = *(const float4*)&pr->sx[r][c];
                    float a = acc[r];
                    a = fmaf(sv.x, w0, a);
                    a = fmaf(sv.y, w1, a);
                    a = fmaf(sv.z, w2, a);
                    a = fmaf(sv.w, w3, a);
                    acc[r] = a;
                }
            }
#pragma unroll
            for (int r = 0; r < 14; r++) pr->res[r][side * 128 + h] = acc[r];
            __syncthreads();

            // repack to fp16 pairs (slot-permuted)
#pragma unroll
            for (int u = 0; u < 7; u++) {
                int idx = tid + 256 * u;          // 0..1791
                int row = idx >> 7;
                if (row < nrows) {
                    int rem = idx & 127;
                    int sd = rem >> 6;
                    int j = rem & 63;
                    __half2 v = __floats2half2_rn(pr->res[row][sd * 128 + 2 * j],
                                                  pr->res[row][sd * 128 + 2 * j + 1]);
                    (sd ? g_aRh : g_aLh)[(size_t)(r0 + row) * 64 + slotperm(j)] = v;
                }
            }
        }

        // W2 convert on CTAs 132..147 (16 CTAs x 256 = 4096 half2)
        if (bid >= 132) {
            int idx = (bid - 132) * 256 + tid;
            int n = idx >> 6;
            int j = idx & 63;
            g_W2h[n * 64 + slotperm(j)] =
                __floats2half2_rn(W2[(2 * j) * H2 + n], W2[(2 * j + 1) * H2 + n]);
        }

        // zero fully-masked 32x16 tiles
        {
            float4* out4 = (float4*)out;
            for (int m = bid; m < NMASK; m += GRID) {
                int bz = (m >= NMASK / 2);
                int mm = m - (bz ? NMASK / 2 : 0);
                int itz = (int)((1.f + sqrtf(1.f + 4.f * (float)mm)) * 0.5f);
                while (itz * (itz + 1) <= mm) itz++;
                while (itz * (itz - 1) > mm) itz--;
                int jtz = mm - itz * (itz - 1);
                if (tid < 128) {
                    int r = tid >> 2, c4 = tid & 3;
                    out4[(size_t)((bz << 10) + itz * TI + r) * 256 + jtz * 4 + c4] =
                        make_float4(0.f, 0.f, 0.f, 0.f);
                }
            }
        }
    }

    // =================== grid barrier (spin, self-resetting) ===================
    __threadfence();
    __syncthreads();
    if (tid == 0) {
        atomicAdd(&g_cnt, 1u);
        while (atomicAdd(&g_cnt, 0u) < (unsigned)GRID) __nanosleep(64);
    }
    __syncthreads();

    // ======================= PHASE B: pair GEMM (R10 body) =======================
    SmemPair* sm = &smu.pair;

    // stage W2 (padded rows) + biases
    {
        const uint2* gW2 = (const uint2*)g_W2h;
        for (int i = tid; i < H2 * 32; i += 256) {
            int r = i >> 5, c = i & 31;
            sm->w2[r * W2_STRIDE + c] = gW2[i];
        }
        if (tid < H2) {
            sm->b2s[tid] = b2[tid];
            sm->w3s[tid] = W3[tid];
        }
    }
    const float b3v = __ldg(&b3[0]);
    __syncthreads();

    // persistent W2 fragments nt 0..3 (64 regs)
    uint32_t w2r[8][4][2];
#pragma unroll
    for (int ks = 0; ks < 8; ks++)
#pragma unroll
        for (int ntl = 0; ntl < 4; ntl++) {
            uint2 bb = sm->w2[(ntl * 8 + p) * W2_STRIDE + 4 * ks + q];
            w2r[ks][ntl][0] = bb.x;
            w2r[ks][ntl][1] = bb.y;
        }

    const int il0 = 4 * wid;
    const int aL_dst0 = tid;
    const int aR_r = tid >> 4;
    const int aR_c = tid & 15;

    auto issue_stage = [&](int buf, int b, int i0, int j0) {
        const uint4* srcL = (const uint4*)(g_aLh + ((size_t)((b << 10) + i0) << 6));
        const uint4* srcR = (const uint4*)(g_aRh + ((size_t)((b << 10) + j0) << 6));
        uint32_t dL = smem_u32(&sm->aL[buf][0]);
        uint32_t dR = smem_u32(&sm->aR[buf][0]);
        cpasync16(dL + (uint32_t)(aL_dst0 * 16), srcL + aL_dst0);
        cpasync16(dL + (uint32_t)((aL_dst0 + 256) * 16), srcL + (aL_dst0 + 256));
        cpasync16(dR + (uint32_t)((aR_r * 17 + aR_c) * 16), srcR + tid);
    };

    int buf = 0;
    int curB = 0, curI0 = 0, curJ0 = 0;
    {
        int a0 = bid;
        if (a0 < NACT) {
            int b = (a0 >= HALF_ACT);
            int aa = a0 - (b ? HALF_ACT : 0);
            int it, jt;
            decode_tile(aa, it, jt);
            curB = b; curI0 = it * TI; curJ0 = jt * TJ;
            issue_stage(0, curB, curI0, curJ0);
        }
        CP_COMMIT();
    }

    for (int a = bid; a < NACT; a += GRID) {
        const int b  = curB;
        const int i0 = curI0;
        const int j0 = curJ0;

        {
            int an = a + GRID;
            if (an < NACT) {
                int bn = (an >= HALF_ACT);
                int aan = an - (bn ? HALF_ACT : 0);
                int itn, jtn;
                decode_tile(aan, itn, jtn);
                curB = bn; curI0 = itn * TI; curJ0 = jtn * TJ;
                issue_stage(buf ^ 1, bn, curI0, curJ0);
            }
            CP_COMMIT();
        }
        CP_WAIT1();
        __syncthreads();

        const uint2* aLb = sm->aL[buf];
        const uint2* aRb = sm->aR[buf];

        float acc[4][8][4];
#pragma unroll
        for (int mt = 0; mt < 4; mt++)
#pragma unroll
            for (int nt = 0; nt < 8; nt++)
#pragma unroll
                for (int e = 0; e < 4; e++) acc[mt][nt][e] = 0.f;

        uint2 Rp_c, Rp8_c, La_c0, La_c1, La_c2, La_c3;
        {
            const int kf = q;
            Rp_c  = aRb[p * AR_STRIDE + kf];
            Rp8_c = aRb[(p + 8) * AR_STRIDE + kf];
            La_c0 = aLb[(il0 + 0) * 32 + kf];
            La_c1 = aLb[(il0 + 1) * 32 + kf];
            La_c2 = aLb[(il0 + 2) * 32 + kf];
            La_c3 = aLb[(il0 + 3) * 32 + kf];
        }
#pragma unroll
        for (int ks = 0; ks < 8; ks++) {
            uint2 Rp_n, Rp8_n, La_n0, La_n1, La_n2, La_n3;
            if (ks < 7) {
                const int kf = 4 * (ks + 1) + q;
                Rp_n  = aRb[p * AR_STRIDE + kf];
                Rp8_n = aRb[(p + 8) * AR_STRIDE + kf];
                La_n0 = aLb[(il0 + 0) * 32 + kf];
                La_n1 = aLb[(il0 + 1) * 32 + kf];
                La_n2 = aLb[(il0 + 2) * 32 + kf];
                La_n3 = aLb[(il0 + 3) * 32 + kf];
            }

            uint32_t a4[4][4];
            {
                uint2 Ls[4] = {La_c0, La_c1, La_c2, La_c3};
#pragma unroll
                for (int mt = 0; mt < 4; mt++) {
                    a4[mt][0] = h2_relu_add(Ls[mt].x, Rp_c.x);
                    a4[mt][1] = h2_relu_add(Ls[mt].x, Rp8_c.x);
                    a4[mt][2] = h2_relu_add(Ls[mt].y, Rp_c.y);
                    a4[mt][3] = h2_relu_add(Ls[mt].y, Rp8_c.y);
                }
            }

#pragma unroll
            for (int ntl = 0; ntl < 4; ntl++)
#pragma unroll
                for (int mt = 0; mt < 4; mt++)
                    mma_f16(acc[mt][ntl], a4[mt],
                            w2r[ks][ntl][0], w2r[ks][ntl][1]);
#pragma unroll
            for (int ntl = 4; ntl < 8; ntl++) {
                uint2 bb = sm->w2[(ntl * 8 + p) * W2_STRIDE + 4 * ks + q];
#pragma unroll
                for (int mt = 0; mt < 4; mt++)
                    mma_f16(acc[mt][ntl], a4[mt], bb.x, bb.y);
            }

            Rp_c = Rp_n; Rp8_c = Rp8_n;
            La_c0 = La_n0; La_c1 = La_n1; La_c2 = La_n2; La_c3 = La_n3;
        }

        // epilogue
#pragma unroll
        for (int mt = 0; mt < 4; mt++) {
            float slo = 0.f, shi = 0.f;
#pragma unroll
            for (int nt = 0; nt < 8; nt++) {
                int g0 = nt * 8 + 2 * q;
                float b20 = sm->b2s[g0], b21 = sm->b2s[g0 + 1];
                float w30 = sm->w3s[g0], w31 = sm->w3s[g0 + 1];
                slo = fmaf(fmaxf(acc[mt][nt][0] + b20, 0.f), w30, slo);
                slo = fmaf(fmaxf(acc[mt][nt][1] + b21, 0.f), w31, slo);
                shi = fmaf(fmaxf(acc[mt][nt][2] + b20, 0.f), w30, shi);
                shi = fmaf(fmaxf(acc[mt][nt][3] + b21, 0.f), w31, shi);
            }
            slo += __shfl_xor_sync(0xFFFFFFFFu, slo, 1);
            slo += __shfl_xor_sync(0xFFFFFFFFu, slo, 2);
            shi += __shfl_xor_sync(0xFFFFFFFFu, shi, 1);
            shi += __shfl_xor_sync(0xFFFFFFFFu, shi, 2);
            if (q == 0) {
                int gi = i0 + il0 + mt;
                int gjlo = j0 + p;
                int gjhi = gjlo + 8;
                size_t base = ((size_t)((b << 10) + gi)) << 10;
                out[base + gjlo] = (gjlo > gi) ? (slo + b3v) : 0.f;
                out[base + gjhi] = (gjhi > gi) ? (shi + b3v) : 0.f;
            }
        }
        __syncthreads();
        buf ^= 1;
    }

    // -------- reset barrier counters for the next graph replay --------
    __syncthreads();
    if (tid == 0) {
        unsigned d = atomicAdd(&g_done, 1u);
        if (d == (unsigned)GRID - 1u) {
            atomicExch(&g_cnt, 0u);
            atomicExch(&g_done, 0u);
            __threadfence();
        }
    }
}

// ---------------------------------------------------------------------------
extern "C" void kernel_launch(void* const* d_in, const int* in_sizes, int n_in,
                              void* d_out, int out_size) {
    const float* x  = (const float*)d_in[0];
    const float* W1 = (const float*)d_in[1];
    const float* b1 = (const float*)d_in[2];
    const float* W2 = (const float*)d_in[3];
    const float* b2 = (const float*)d_in[4];
    const float* W3 = (const float*)d_in[5];
    const float* b3 = (const float*)d_in[6];
    float* out = (float*)d_out;

    fused_kernel<<<GRID, 256>>>(x, W1, b1, W2, b2, W3, b3, out);
}

// round 13
// speedup vs baseline: 1.0677x; 1.0448x over previous
#include <cuda_runtime.h>
#include <cuda_fp16.h>
#include <cstdint>

// B=2, N=1024, C=128, H1=128, H2=64
//   aL[b,i,h] = x[b,i]@W1[:C] + b1 ; aR[b,j,h] = x[b,j]@W1[C:]
//   y[b,i,j] = relu(relu(aL_i + aR_j) @ W2 + b2) @ W3 + b3   (j>i else 0)
// R13 = R12 fused kernel with the tail fixed:
//  - grid = multiProcessorCount (152 on GB300): max 14 tiles/CTA (was 15@148)
//  - phase A: rows on CTAs 0..146, W2 convert on idle CTAs 147+ (less straggle)
//  - all strides/barrier counts generic in gridDim.x (no deadlock any SM count)

#define Bb 2
#define Nn 1024
#define Cc 128
#define H1 128
#define H2 64

#define TI 32
#define TJ 16
#define NACT  2112     // active tiles: 2 * 1056
#define NMASK 1984     // fully-masked tiles: 2 * 992
#define HALF_ACT 1056

// scratch (device globals; fp16 pairs, k-permuted)
__device__ __align__(16) __half2 g_aLh[Bb * Nn * 64];
__device__ __align__(16) __half2 g_aRh[Bb * Nn * 64];
__device__ __align__(16) __half2 g_W2h[H2 * 64];
__device__ unsigned g_cnt = 0u;
__device__ unsigned g_done = 0u;

__device__ __forceinline__ int slotperm(int j) {
    int jj = j & 7;
    return (j & ~7) | (jj < 4 ? (jj << 1) : (((jj - 4) << 1) | 1));
}

__device__ __forceinline__ uint32_t h2_relu_add(uint32_t x, uint32_t y) {
    __half2 a = *reinterpret_cast<__half2*>(&x);
    __half2 b = *reinterpret_cast<__half2*>(&y);
    __half2 r = __hmax2(__hadd2(a, b), __float2half2_rn(0.f));
    return *reinterpret_cast<uint32_t*>(&r);
}

__device__ __forceinline__ void mma_f16(float c[4], const uint32_t a[4],
                                        uint32_t b0, uint32_t b1) {
    asm volatile(
        "mma.sync.aligned.m16n8k16.row.col.f32.f16.f16.f32 "
        "{%0,%1,%2,%3},{%4,%5,%6,%7},{%8,%9},{%0,%1,%2,%3};"
        : "+f"(c[0]), "+f"(c[1]), "+f"(c[2]), "+f"(c[3])
        : "r"(a[0]), "r"(a[1]), "r"(a[2]), "r"(a[3]), "r"(b0), "r"(b1));
}

__device__ __forceinline__ uint32_t smem_u32(const void* p) {
    uint32_t a;
    asm("{ .reg .u64 t; cvta.to.shared.u64 t, %1; cvt.u32.u64 %0, t; }"
        : "=r"(a) : "l"(p));
    return a;
}
__device__ __forceinline__ void cpasync16(uint32_t dst, const void* src) {
    asm volatile("cp.async.cg.shared.global [%0], [%1], 16;"
                 :: "r"(dst), "l"(src));
}
#define CP_COMMIT() asm volatile("cp.async.commit_group;" ::: "memory")
#define CP_WAIT1()  asm volatile("cp.async.wait_group 1;" ::: "memory")

#define AR_STRIDE 34
#define W2_STRIDE 34

struct SmemPair {
    uint2 w2[H2 * W2_STRIDE];     // 17408 B
    uint2 aL[2][TI * 32];         // 2 x 8192 B
    uint2 aR[2][TJ * AR_STRIDE];  // 2 x 4352 B
    float b2s[H2];
    float w3s[H2];
};
struct SmemPrep {
    float sx[14][Cc];             // 7168 B
    float res[14][256];           // 14336 B
};
union SmemAll {
    SmemPair pair;
    SmemPrep prep;
};

__device__ __forceinline__ void decode_tile(int aa, int& it, int& jt) {
    it = (int)((65.f - sqrtf(4225.f - 4.f * (float)aa)) * 0.5f);
    while ((it + 1) * (64 - it) <= aa) it++;
    while (it * (65 - it) > aa) it--;
    jt = 2 * it + (aa - it * (65 - it));
}

__global__ void __launch_bounds__(256)
fused_kernel(const float* __restrict__ x,
             const float* __restrict__ W1,
             const float* __restrict__ b1,
             const float* __restrict__ W2,
             const float* __restrict__ b2,
             const float* __restrict__ W3,
             const float* __restrict__ b3,
             float* __restrict__ out) {
    __shared__ SmemAll smu;

    const int tid = threadIdx.x;
    const int bid = blockIdx.x;
    const int nblk = gridDim.x;
    const int wid = tid >> 5;
    const int lane = tid & 31;
    const int p = lane >> 2;
    const int q = lane & 3;

    // ======================= PHASE A: prep =======================
    {
        SmemPrep* pr = &smu.prep;
        const int r0 = bid * 14;
        const int nrows = min(14, Bb * Nn - r0);

        if (nrows > 0) {
            const float4* x4 = (const float4*)x;
            const int nchunks = nrows * 32;
#pragma unroll
            for (int u = 0; u < 2; u++) {
                int c = tid + 256 * u;
                if (c < nchunks)
                    ((float4*)pr->sx)[c] = x4[r0 * 32 + c];
            }
            __syncthreads();

            const int side = tid >> 7;
            const int h = tid & 127;
            const float* Wp = W1 + (side ? (Cc * H1 + h) : h);
            float acc[14];
            const float init = side ? 0.f : b1[h];
#pragma unroll
            for (int r = 0; r < 14; r++) acc[r] = init;

#pragma unroll 4
            for (int c = 0; c < Cc; c += 4) {
                float w0 = __ldg(&Wp[(c + 0) * H1]);
                float w1 = __ldg(&Wp[(c + 1) * H1]);
                float w2 = __ldg(&Wp[(c + 2) * H1]);
                float w3 = __ldg(&Wp[(c + 3) * H1]);
#pragma unroll
                for (int r = 0; r < 14; r++) {
                    float4 sv = *(const float4*)&pr->sx[r][c];
                    float a = acc[r];
                    a = fmaf(sv.x, w0, a);
                    a = fmaf(sv.y, w1, a);
                    a = fmaf(sv.z, w2, a);
                    a = fmaf(sv.w, w3, a);
                    acc[r] = a;
                }
            }
#pragma unroll
            for (int r = 0; r < 14; r++) pr->res[r][side * 128 + h] = acc[r];
            __syncthreads();

#pragma unroll
            for (int u = 0; u < 7; u++) {
                int idx = tid + 256 * u;          // 0..1791
                int row = idx >> 7;
                if (row < nrows) {
                    int rem = idx & 127;
                    int sd = rem >> 6;
                    int j = rem & 63;
                    __half2 v = __floats2half2_rn(pr->res[row][sd * 128 + 2 * j],
                                                  pr->res[row][sd * 128 + 2 * j + 1]);
                    (sd ? g_aRh : g_aLh)[(size_t)(r0 + row) * 64 + slotperm(j)] = v;
                }
            }
        } else {
            // idle-row CTAs (bid >= 147): W2 convert (4096 half2)
            for (int idx = (bid - 147) * 256 + tid; idx < H2 * 64;
                 idx += (nblk - 147) * 256) {
                int n = idx >> 6;
                int j = idx & 63;
                g_W2h[n * 64 + slotperm(j)] =
                    __floats2half2_rn(W2[(2 * j) * H2 + n],
                                      W2[(2 * j + 1) * H2 + n]);
            }
        }

        // zero fully-masked 32x16 tiles
        {
            float4* out4 = (float4*)out;
            for (int m = bid; m < NMASK; m += nblk) {
                int bz = (m >= NMASK / 2);
                int mm = m - (bz ? NMASK / 2 : 0);
                int itz = (int)((1.f + sqrtf(1.f + 4.f * (float)mm)) * 0.5f);
                while (itz * (itz + 1) <= mm) itz++;
                while (itz * (itz - 1) > mm) itz--;
                int jtz = mm - itz * (itz - 1);
                if (tid < 128) {
                    int r = tid >> 2, c4 = tid & 3;
                    out4[(size_t)((bz << 10) + itz * TI + r) * 256 + jtz * 4 + c4] =
                        make_float4(0.f, 0.f, 0.f, 0.f);
                }
            }
        }
    }

    // =================== grid barrier (spin, self-resetting) ===================
    __threadfence();
    __syncthreads();
    if (tid == 0) {
        atomicAdd(&g_cnt, 1u);
        while (atomicAdd(&g_cnt, 0u) < (unsigned)nblk) __nanosleep(64);
    }
    __syncthreads();

    // ======================= PHASE B: pair GEMM (R10 body) =======================
    SmemPair* sm = &smu.pair;

    {
        const uint2* gW2 = (const uint2*)g_W2h;
        for (int i = tid; i < H2 * 32; i += 256) {
            int r = i >> 5, c = i & 31;
            sm->w2[r * W2_STRIDE + c] = gW2[i];
        }
        if (tid < H2) {
            sm->b2s[tid] = b2[tid];
            sm->w3s[tid] = W3[tid];
        }
    }
    const float b3v = __ldg(&b3[0]);
    __syncthreads();

    uint32_t w2r[8][4][2];
#pragma unroll
    for (int ks = 0; ks < 8; ks++)
#pragma unroll
        for (int ntl = 0; ntl < 4; ntl++) {
            uint2 bb = sm->w2[(ntl * 8 + p) * W2_STRIDE + 4 * ks + q];
            w2r[ks][ntl][0] = bb.x;
            w2r[ks][ntl][1] = bb.y;
        }

    const int il0 = 4 * wid;
    const int aL_dst0 = tid;
    const int aR_r = tid >> 4;
    const int aR_c = tid & 15;

    auto issue_stage = [&](int buf, int b, int i0, int j0) {
        const uint4* srcL = (const uint4*)(g_aLh + ((size_t)((b << 10) + i0) << 6));
        const uint4* srcR = (const uint4*)(g_aRh + ((size_t)((b << 10) + j0) << 6));
        uint32_t dL = smem_u32(&sm->aL[buf][0]);
        uint32_t dR = smem_u32(&sm->aR[buf][0]);
        cpasync16(dL + (uint32_t)(aL_dst0 * 16), srcL + aL_dst0);
        cpasync16(dL + (uint32_t)((aL_dst0 + 256) * 16), srcL + (aL_dst0 + 256));
        cpasync16(dR + (uint32_t)((aR_r * 17 + aR_c) * 16), srcR + tid);
    };

    int buf = 0;
    int curB = 0, curI0 = 0, curJ0 = 0;
    {
        int a0 = bid;
        if (a0 < NACT) {
            int b = (a0 >= HALF_ACT);
            int aa = a0 - (b ? HALF_ACT : 0);
            int it, jt;
            decode_tile(aa, it, jt);
            curB = b; curI0 = it * TI; curJ0 = jt * TJ;
            issue_stage(0, curB, curI0, curJ0);
        }
        CP_COMMIT();
    }

    for (int a = bid; a < NACT; a += nblk) {
        const int b  = curB;
        const int i0 = curI0;
        const int j0 = curJ0;

        {
            int an = a + nblk;
            if (an < NACT) {
                int bn = (an >= HALF_ACT);
                int aan = an - (bn ? HALF_ACT : 0);
                int itn, jtn;
                decode_tile(aan, itn, jtn);
                curB = bn; curI0 = itn * TI; curJ0 = jtn * TJ;
                issue_stage(buf ^ 1, bn, curI0, curJ0);
            }
            CP_COMMIT();
        }
        CP_WAIT1();
        __syncthreads();

        const uint2* aLb = sm->aL[buf];
        const uint2* aRb = sm->aR[buf];

        float acc[4][8][4];
#pragma unroll
        for (int mt = 0; mt < 4; mt++)
#pragma unroll
            for (int nt = 0; nt < 8; nt++)
#pragma unroll
                for (int e = 0; e < 4; e++) acc[mt][nt][e] = 0.f;

        uint2 Rp_c, Rp8_c, La_c0, La_c1, La_c2, La_c3;
        {
            const int kf = q;
            Rp_c  = aRb[p * AR_STRIDE + kf];
            Rp8_c = aRb[(p + 8) * AR_STRIDE + kf];
            La_c0 = aLb[(il0 + 0) * 32 + kf];
            La_c1 = aLb[(il0 + 1) * 32 + kf];
            La_c2 = aLb[(il0 + 2) * 32 + kf];
            La_c3 = aLb[(il0 + 3) * 32 + kf];
        }
#pragma unroll
        for (int ks = 0; ks < 8; ks++) {
            uint2 Rp_n, Rp8_n, La_n0, La_n1, La_n2, La_n3;
            if (ks < 7) {
                const int kf = 4 * (ks + 1) + q;
                Rp_n  = aRb[p * AR_STRIDE + kf];
                Rp8_n = aRb[(p + 8) * AR_STRIDE + kf];
                La_n0 = aLb[(il0 + 0) * 32 + kf];
                La_n1 = aLb[(il0 + 1) * 32 + kf];
                La_n2 = aLb[(il0 + 2) * 32 + kf];
                La_n3 = aLb[(il0 + 3) * 32 + kf];
            }

            uint32_t a4[4][4];
            {
                uint2 Ls[4] = {La_c0, La_c1, La_c2, La_c3};
#pragma unroll
                for (int mt = 0; mt < 4; mt++) {
                    a4[mt][0] = h2_relu_add(Ls[mt].x, Rp_c.x);
                    a4[mt][1] = h2_relu_add(Ls[mt].x, Rp8_c.x);
                    a4[mt][2] = h2_relu_add(Ls[mt].y, Rp_c.y);
                    a4[mt][3] = h2_relu_add(Ls[mt].y, Rp8_c.y);
                }
            }

#pragma unroll
            for (int ntl = 0; ntl < 4; ntl++)
#pragma unroll
                for (int mt = 0; mt < 4; mt++)
                    mma_f16(acc[mt][ntl], a4[mt],
                            w2r[ks][ntl][0], w2r[ks][ntl][1]);
#pragma unroll
            for (int ntl = 4; ntl < 8; ntl++) {
                uint2 bb = sm->w2[(ntl * 8 + p) * W2_STRIDE + 4 * ks + q];
#pragma unroll
                for (int mt = 0; mt < 4; mt++)
                    mma_f16(acc[mt][ntl], a4[mt], bb.x, bb.y);
            }

            Rp_c = Rp_n; Rp8_c = Rp8_n;
            La_c0 = La_n0; La_c1 = La_n1; La_c2 = La_n2; La_c3 = La_n3;
        }

        // epilogue
#pragma unroll
        for (int mt = 0; mt < 4; mt++) {
            float slo = 0.f, shi = 0.f;
#pragma unroll
            for (int nt = 0; nt < 8; nt++) {
                int g0 = nt * 8 + 2 * q;
                float b20 = sm->b2s[g0], b21 = sm->b2s[g0 + 1];
                float w30 = sm->w3s[g0], w31 = sm->w3s[g0 + 1];
                slo = fmaf(fmaxf(acc[mt][nt][0] + b20, 0.f), w30, slo);
                slo = fmaf(fmaxf(acc[mt][nt][1] + b21, 0.f), w31, slo);
                shi = fmaf(fmaxf(acc[mt][nt][2] + b20, 0.f), w30, shi);
                shi = fmaf(fmaxf(acc[mt][nt][3] + b21, 0.f), w31, shi);
            }
            slo += __shfl_xor_sync(0xFFFFFFFFu, slo, 1);
            slo += __shfl_xor_sync(0xFFFFFFFFu, slo, 2);
            shi += __shfl_xor_sync(0xFFFFFFFFu, shi, 1);
            shi += __shfl_xor_sync(0xFFFFFFFFu, shi, 2);
            if (q == 0) {
                int gi = i0 + il0 + mt;
                int gjlo = j0 + p;
                int gjhi = gjlo + 8;
                size_t base = ((size_t)((b << 10) + gi)) << 10;
                out[base + gjlo] = (gjlo > gi) ? (slo + b3v) : 0.f;
                out[base + gjhi] = (gjhi > gi) ? (shi + b3v) : 0.f;
            }
        }
        __syncthreads();
        buf ^= 1;
    }

    // -------- reset barrier counters for the next graph replay --------
    __syncthreads();
    if (tid == 0) {
        unsigned d = atomicAdd(&g_done, 1u);
        if (d == (unsigned)nblk - 1u) {
            atomicExch(&g_cnt, 0u);
            atomicExch(&g_done, 0u);
            __threadfence();
        }
    }
}

// ---------------------------------------------------------------------------
extern "C" void kernel_launch(void* const* d_in, const int* in_sizes, int n_in,
                              void* d_out, int out_size) {
    const float* x  = (const float*)d_in[0];
    const float* W1 = (const float*)d_in[1];
    const float* b1 = (const float*)d_in[2];
    const float* W2 = (const float*)d_in[3];
    const float* b2 = (const float*)d_in[4];
    const float* W3 = (const float*)d_in[5];
    const float* b3 = (const float*)d_in[6];
    float* out = (float*)d_out;

    int sms = 148;
    cudaDeviceGetAttribute(&sms, cudaDevAttrMultiProcessorCount, 0);
    if (sms < 148) sms = 148;   // co-residency still holds (1 CTA/SM on >=148-SM parts)

    fused_kernel<<<sms, 256>>>(x, W1, b1, W2, b2, W3, b3, out);
}

// round 14
// speedup vs baseline: 1.0917x; 1.0224x over previous
#include <cuda_runtime.h>
#include <cuda_fp16.h>
#include <cstdint>

// B=2, N=1024, C=128, H1=128, H2=64
//   aL[b,i,h] = x[b,i]@W1[:C] + b1 ; aR[b,j,h] = x[b,j]@W1[C:]
//   y[b,i,j] = relu(relu(aL_i + aR_j) @ W2 + b2) @ W3 + b3   (j>i else 0)
// R14: warp-autonomous tiles. Each warp owns an independent 4i x 16j tile
// stream with PRIVATE double-buffered aL/aR (own cp.async + wait_group +
// syncwarp). NO __syncthreads in the tile loop -> warps on an SMSP de-phase,
// one warp's epilogue/staging overlaps the other's MMAs (R13: tensor pipe
// at throughput limit while busy, but idle ~50% due to lockstep barriers).

#define Bb 2
#define Nn 1024
#define Cc 128
#define H1 128
#define H2 64

#define NACT4 16640    // active 4x16 warp-tiles: 2 * 8320
#define HALF4 8320

// scratch (device globals; fp16 pairs, k-permuted)
__device__ __align__(16) __half2 g_aLh[Bb * Nn * 64];
__device__ __align__(16) __half2 g_aRh[Bb * Nn * 64];
__device__ __align__(16) __half2 g_W2h[H2 * 64];
__device__ unsigned g_cnt = 0u;
__device__ unsigned g_done = 0u;

__device__ __forceinline__ int slotperm(int j) {
    int jj = j & 7;
    return (j & ~7) | (jj < 4 ? (jj << 1) : (((jj - 4) << 1) | 1));
}

__device__ __forceinline__ uint32_t h2_relu_add(uint32_t x, uint32_t y) {
    __half2 a = *reinterpret_cast<__half2*>(&x);
    __half2 b = *reinterpret_cast<__half2*>(&y);
    __half2 r = __hmax2(__hadd2(a, b), __float2half2_rn(0.f));
    return *reinterpret_cast<uint32_t*>(&r);
}

__device__ __forceinline__ void mma_f16(float c[4], const uint32_t a[4],
                                        uint32_t b0, uint32_t b1) {
    asm volatile(
        "mma.sync.aligned.m16n8k16.row.col.f32.f16.f16.f32 "
        "{%0,%1,%2,%3},{%4,%5,%6,%7},{%8,%9},{%0,%1,%2,%3};"
        : "+f"(c[0]), "+f"(c[1]), "+f"(c[2]), "+f"(c[3])
        : "r"(a[0]), "r"(a[1]), "r"(a[2]), "r"(a[3]), "r"(b0), "r"(b1));
}

__device__ __forceinline__ uint32_t smem_u32(const void* p) {
    uint32_t a;
    asm("{ .reg .u64 t; cvta.to.shared.u64 t, %1; cvt.u32.u64 %0, t; }"
        : "=r"(a) : "l"(p));
    return a;
}
__device__ __forceinline__ void cpasync16(uint32_t dst, const void* src) {
    asm volatile("cp.async.cg.shared.global [%0], [%1], 16;"
                 :: "r"(dst), "l"(src));
}
#define CP_COMMIT() asm volatile("cp.async.commit_group;" ::: "memory")
#define CP_WAIT1()  asm volatile("cp.async.wait_group 1;" ::: "memory")

#define AR_STRIDE 34     // uint2 per aR row (17 uint4)
#define W2_STRIDE 34

// dynamic smem layout (bytes):
//   [0, 17408)            W2 rows 0..63 (uint2[64*34])
//   [17408, 17664)        b2s (64 f32)
//   [17664, 17920)        w3s (64 f32)
//   [17920 + w*10752):    warp w private:
//        aL buf0 @ +0     (128 uint2 = 1024B)   4 rows x 32 uint2
//        aL buf1 @ +1024
//        aR buf0 @ +2048  (544 uint2 = 4352B)   16 rows x 34 uint2
//        aR buf1 @ +6400
#define SM_B2_OFF   17408
#define SM_W3_OFF   17664
#define SM_WARP_OFF 17920
#define WARP_BYTES  10752
#define SMEM_TOTAL  (SM_WARP_OFF + 8 * WARP_BYTES)   // 103936

// decode warp-tile index (4i x 16j, active iff jt >= it>>2):
// group g = it>>2 in [0,64), C(g) = 258g - 2g^2 tiles before group g
__device__ __forceinline__ void decode4(int a, int& b, int& i0, int& j0) {
    b = (a >= HALF4);
    int aa = a - (b ? HALF4 : 0);
    int g = (int)((258.f - sqrtf(66564.f - 8.f * (float)aa)) * 0.25f);
    if (g < 0) g = 0;
    if (g > 63) g = 63;
    while (g < 63 && 258 * (g + 1) - 2 * (g + 1) * (g + 1) <= aa) g++;
    while (g > 0 && 258 * g - 2 * g * g > aa) g--;
    int rem = aa - (258 * g - 2 * g * g);
    int cnt = 64 - g;
    int io = rem / cnt;
    j0 = (g + rem - io * cnt) << 4;
    i0 = (g << 4) + (io << 2);
}

__global__ void __launch_bounds__(256)
fused_kernel(const float* __restrict__ x,
             const float* __restrict__ W1,
             const float* __restrict__ b1,
             const float* __restrict__ W2,
             const float* __restrict__ b2,
             const float* __restrict__ W3,
             const float* __restrict__ b3,
             float* __restrict__ out) {
    extern __shared__ char smraw[];

    const int tid = threadIdx.x;
    const int bid = blockIdx.x;
    const int nblk = gridDim.x;
    const int wid = tid >> 5;
    const int lane = tid & 31;
    const int p = lane >> 2;
    const int q = lane & 3;

    // ======================= PHASE A: prep =======================
    {
        float* sx = (float*)smraw;               // [14][128]
        float* res = (float*)(smraw + 7168);     // [14][256]
        const int r0 = bid * 14;
        const int nrows = min(14, Bb * Nn - r0);

        if (nrows > 0) {
            const float4* x4 = (const float4*)x;
            const int nchunks = nrows * 32;
#pragma unroll
            for (int u = 0; u < 2; u++) {
                int c = tid + 256 * u;
                if (c < nchunks)
                    ((float4*)sx)[c] = x4[r0 * 32 + c];
            }
            __syncthreads();

            const int side = tid >> 7;
            const int h = tid & 127;
            const float* Wp = W1 + (side ? (Cc * H1 + h) : h);
            float acc[14];
            const float init = side ? 0.f : b1[h];
#pragma unroll
            for (int r = 0; r < 14; r++) acc[r] = init;

#pragma unroll 4
            for (int c = 0; c < Cc; c += 4) {
                float w0 = __ldg(&Wp[(c + 0) * H1]);
                float w1 = __ldg(&Wp[(c + 1) * H1]);
                float w2 = __ldg(&Wp[(c + 2) * H1]);
                float w3 = __ldg(&Wp[(c + 3) * H1]);
#pragma unroll
                for (int r = 0; r < 14; r++) {
                    const float* sxr = sx + r * Cc + c;
                    float4 sv = *(const float4*)sxr;
                    float a = acc[r];
                    a = fmaf(sv.x, w0, a);
                    a = fmaf(sv.y, w1, a);
                    a = fmaf(sv.z, w2, a);
                    a = fmaf(sv.w, w3, a);
                    acc[r] = a;
                }
            }
#pragma unroll
            for (int r = 0; r < 14; r++) res[r * 256 + side * 128 + h] = acc[r];
            __syncthreads();

#pragma unroll
            for (int u = 0; u < 7; u++) {
                int idx = tid + 256 * u;          // 0..1791
                int row = idx >> 7;
                if (row < nrows) {
                    int rem = idx & 127;
                    int sd = rem >> 6;
                    int j = rem & 63;
                    __half2 v = __floats2half2_rn(res[row * 256 + sd * 128 + 2 * j],
                                                  res[row * 256 + sd * 128 + 2 * j + 1]);
                    (sd ? g_aRh : g_aLh)[(size_t)(r0 + row) * 64 + slotperm(j)] = v;
                }
            }
        } else {
            // idle-row CTAs: W2 convert (4096 half2)
            for (int idx = (bid - 147) * 256 + tid; idx < H2 * 64;
                 idx += (nblk - 147) * 256) {
                int n = idx >> 6;
                int j = idx & 63;
                g_W2h[n * 64 + slotperm(j)] =
                    __floats2half2_rn(W2[(2 * j) * H2 + n],
                                      W2[(2 * j + 1) * H2 + n]);
            }
        }

        // zero masked region, row-based: row (b,i) has j < 16*(i>>4) masked
        // beyond what active 4x16 tiles cover
        {
            float4* out4 = (float4*)out;
            const float4 z4 = make_float4(0.f, 0.f, 0.f, 0.f);
            for (int r = bid; r < Bb * Nn; r += nblk) {
                int i = r & (Nn - 1);
                int n4 = 4 * (i >> 4);            // float4 count
                float4* dst = out4 + ((size_t)r << 8);
                for (int c = tid; c < n4; c += 256) dst[c] = z4;
            }
        }
    }

    // =================== grid barrier (spin, self-resetting) ===================
    __threadfence();
    __syncthreads();
    if (tid == 0) {
        atomicAdd(&g_cnt, 1u);
        while (atomicAdd(&g_cnt, 0u) < (unsigned)nblk) __nanosleep(64);
    }
    __syncthreads();

    // ======================= PHASE B: warp-autonomous pair GEMM =======================
    uint2* w2s = (uint2*)smraw;
    float* b2s = (float*)(smraw + SM_B2_OFF);
    float* w3s = (float*)(smraw + SM_W3_OFF);

    {
        const uint2* gW2 = (const uint2*)g_W2h;
        for (int i = tid; i < H2 * 32; i += 256) {
            int r = i >> 5, c = i & 31;
            w2s[r * W2_STRIDE + c] = gW2[i];
        }
        if (tid < H2) {
            b2s[tid] = b2[tid];
            w3s[tid] = W3[tid];
        }
    }
    const float b3v = __ldg(&b3[0]);
    __syncthreads();      // last CTA-wide barrier; warps free-run after this

    // persistent W2 fragments nt 0..3 (64 regs)
    uint32_t w2r[8][4][2];
#pragma unroll
    for (int ks = 0; ks < 8; ks++)
#pragma unroll
        for (int ntl = 0; ntl < 4; ntl++) {
            uint2 bb = w2s[(ntl * 8 + p) * W2_STRIDE + 4 * ks + q];
            w2r[ks][ntl][0] = bb.x;
            w2r[ks][ntl][1] = bb.y;
        }

    // warp-private buffers
    char* wb = smraw + SM_WARP_OFF + wid * WARP_BYTES;
    const uint32_t wL32 = smem_u32(wb);
    const uint32_t wR32 = wL32 + 2048;
    uint2* aLbase = (uint2*)wb;                       // [buf*128 + ...]
    uint2* aRbase = (uint2*)(wb + 2048);              // [buf*544 + ...]

    // stage tile (b,i0,j0) into private buffer `bf` (10 cp.async per lane)
    auto issue_stage = [&](int bf, int b, int i0, int j0) {
        const uint4* srcL = (const uint4*)(g_aLh + ((size_t)((b << 10) + i0) << 6));
        const uint4* srcR = (const uint4*)(g_aRh + ((size_t)((b << 10) + j0) << 6));
        uint32_t dL = wL32 + (uint32_t)bf * 1024u;
        uint32_t dR = wR32 + (uint32_t)bf * 4352u;
        cpasync16(dL + (uint32_t)lane * 16u, srcL + lane);
        cpasync16(dL + (uint32_t)(lane + 32) * 16u, srcL + lane + 32);
#pragma unroll
        for (int u = 0; u < 8; u++) {
            int c = lane + 32 * u;
            int row = c >> 4, col = c & 15;
            cpasync16(dR + (uint32_t)(row * 17 + col) * 16u, srcR + c);
        }
    };

    int a = bid * 8 + wid;
    const int astep = nblk * 8;
    int buf = 0;
    int curB = 0, curI0 = 0, curJ0 = 0;
    if (a < NACT4) {
        decode4(a, curB, curI0, curJ0);
        issue_stage(0, curB, curI0, curJ0);
    }
    CP_COMMIT();

    for (; a < NACT4; a += astep) {
        const int b  = curB;
        const int i0 = curI0;
        const int j0 = curJ0;

        {
            int an = a + astep;
            if (an < NACT4) {
                decode4(an, curB, curI0, curJ0);
                issue_stage(buf ^ 1, curB, curI0, curJ0);
            }
            CP_COMMIT();
        }
        CP_WAIT1();
        __syncwarp();     // warp-private buffer visible to all lanes

        const uint2* aLb = aLbase + buf * 128;
        const uint2* aRb = aRbase + buf * 544;

        float acc[4][8][4];
#pragma unroll
        for (int mt = 0; mt < 4; mt++)
#pragma unroll
            for (int nt = 0; nt < 8; nt++)
#pragma unroll
                for (int e = 0; e < 4; e++) acc[mt][nt][e] = 0.f;

        // kstep loop with one-stage register pipeline
        uint2 Rp_c, Rp8_c, La_c0, La_c1, La_c2, La_c3;
        {
            const int kf = q;
            Rp_c  = aRb[p * AR_STRIDE + kf];
            Rp8_c = aRb[(p + 8) * AR_STRIDE + kf];
            La_c0 = aLb[0 * 32 + kf];
            La_c1 = aLb[1 * 32 + kf];
            La_c2 = aLb[2 * 32 + kf];
            La_c3 = aLb[3 * 32 + kf];
        }
#pragma unroll
        for (int ks = 0; ks < 8; ks++) {
            uint2 Rp_n, Rp8_n, La_n0, La_n1, La_n2, La_n3;
            if (ks < 7) {
                const int kf = 4 * (ks + 1) + q;
                Rp_n  = aRb[p * AR_STRIDE + kf];
                Rp8_n = aRb[(p + 8) * AR_STRIDE + kf];
                La_n0 = aLb[0 * 32 + kf];
                La_n1 = aLb[1 * 32 + kf];
                La_n2 = aLb[2 * 32 + kf];
                La_n3 = aLb[3 * 32 + kf];
            }

            uint32_t a4[4][4];
            {
                uint2 Ls[4] = {La_c0, La_c1, La_c2, La_c3};
#pragma unroll
                for (int mt = 0; mt < 4; mt++) {
                    a4[mt][0] = h2_relu_add(Ls[mt].x, Rp_c.x);
                    a4[mt][1] = h2_relu_add(Ls[mt].x, Rp8_c.x);
                    a4[mt][2] = h2_relu_add(Ls[mt].y, Rp_c.y);
                    a4[mt][3] = h2_relu_add(Ls[mt].y, Rp8_c.y);
                }
            }

#pragma unroll
            for (int ntl = 0; ntl < 4; ntl++)
#pragma unroll
                for (int mt = 0; mt < 4; mt++)
                    mma_f16(acc[mt][ntl], a4[mt],
                            w2r[ks][ntl][0], w2r[ks][ntl][1]);
#pragma unroll
            for (int ntl = 4; ntl < 8; ntl++) {
                uint2 bb = w2s[(ntl * 8 + p) * W2_STRIDE + 4 * ks + q];
#pragma unroll
                for (int mt = 0; mt < 4; mt++)
                    mma_f16(acc[mt][ntl], a4[mt], bb.x, bb.y);
            }

            Rp_c = Rp_n; Rp8_c = Rp8_n;
            La_c0 = La_n0; La_c1 = La_n1; La_c2 = La_n2; La_c3 = La_n3;
        }

        // epilogue: y = b3 + sum_g relu(D+b2)*W3 ; quad reduction
#pragma unroll
        for (int mt = 0; mt < 4; mt++) {
            float slo = 0.f, shi = 0.f;
#pragma unroll
            for (int nt = 0; nt < 8; nt++) {
                int g0 = nt * 8 + 2 * q;
                float b20 = b2s[g0], b21 = b2s[g0 + 1];
                float w30 = w3s[g0], w31 = w3s[g0 + 1];
                slo = fmaf(fmaxf(acc[mt][nt][0] + b20, 0.f), w30, slo);
                slo = fmaf(fmaxf(acc[mt][nt][1] + b21, 0.f), w31, slo);
                shi = fmaf(fmaxf(acc[mt][nt][2] + b20, 0.f), w30, shi);
                shi = fmaf(fmaxf(acc[mt][nt][3] + b21, 0.f), w31, shi);
            }
            slo += __shfl_xor_sync(0xFFFFFFFFu, slo, 1);
            slo += __shfl_xor_sync(0xFFFFFFFFu, slo, 2);
            shi += __shfl_xor_sync(0xFFFFFFFFu, shi, 1);
            shi += __shfl_xor_sync(0xFFFFFFFFu, shi, 2);
            if (q == 0) {
                int gi = i0 + mt;
                int gjlo = j0 + p;
                int gjhi = gjlo + 8;
                size_t base = ((size_t)((b << 10) + gi)) << 10;
                out[base + gjlo] = (gjlo > gi) ? (slo + b3v) : 0.f;
                out[base + gjhi] = (gjhi > gi) ? (shi + b3v) : 0.f;
            }
        }
        buf ^= 1;    // private buffers: no CTA barrier needed
    }

    // -------- reset barrier counters for the next graph replay --------
    __syncthreads();
    if (tid == 0) {
        unsigned d = atomicAdd(&g_done, 1u);
        if (d == (unsigned)nblk - 1u) {
            atomicExch(&g_cnt, 0u);
            atomicExch(&g_done, 0u);
            __threadfence();
        }
    }
}

// ---------------------------------------------------------------------------
extern "C" void kernel_launch(void* const* d_in, const int* in_sizes, int n_in,
                              void* d_out, int out_size) {
    const float* x  = (const float*)d_in[0];
    const float* W1 = (const float*)d_in[1];
    const float* b1 = (const float*)d_in[2];
    const float* W2 = (const float*)d_in[3];
    const float* b2 = (const float*)d_in[4];
    const float* W3 = (const float*)d_in[5];
    const float* b3 = (const float*)d_in[6];
    float* out = (float*)d_out;

    static bool attr_set = false;
    if (!attr_set) {
        cudaFuncSetAttribute(fused_kernel,
                             cudaFuncAttributeMaxDynamicSharedMemorySize,
                             SMEM_TOTAL);
        attr_set = true;
    }

    int sms = 148;
    cudaDeviceGetAttribute(&sms, cudaDevAttrMultiProcessorCount, 0);
    if (sms < 148) sms = 148;

    fused_kernel<<<sms, 256, SMEM_TOTAL>>>(x, W1, b1, W2, b2, W3, b3, out);
}